// round 1
// baseline (speedup 1.0000x reference)
#include <cuda_runtime.h>
#include <cstdint>

#define Bn   64
#define Cc   256
#define Hh   28
#define Ww   28
#define HW   784
#define NPIX 50176            // Bn*HW
#define KTOT 2304             // Cc*9
#define NELEM 12845056        // Bn*Cc*HW

#define BM 128
#define BN 128
#define BK 64
#define AST 80                // smem row stride (bytes) -> bank-conflict-free frag reads
#define NKI 36                // KTOT/BK

// ---------------- scratch (static device allocations; allowed) ----------------
__device__ int8_t g_xq[NPIX*Cc];
__device__ int8_t g_hq[NPIX*Cc];
__device__ int8_t g_wq1[Cc*KTOT];
__device__ int8_t g_wq2[Cc*KTOT];
__device__ float  g_h [NPIX*Cc];
__device__ float  g_y2[NPIX*Cc];
__device__ float  g_inv1[Cc], g_bias1[Cc], g_inv2[Cc], g_bias2[Cc];
__device__ unsigned g_maxbits[4];   // 0:x 1:w1 2:w2 3:h   (fabs bits; uint order == float order)
__device__ float  g_scale[3];       // s_x, s_w1, s_w2  (= alpha/7, fp32 div to match JAX bitwise)

// ---------------- helpers ----------------
__device__ __forceinline__ void cp16(void* sm, const void* g, bool v){
  unsigned sa = (unsigned)__cvta_generic_to_shared(sm);
  int sz = v ? 16 : 0;
  asm volatile("cp.async.cg.shared.global [%0], [%1], 16, %2;\n" :: "r"(sa), "l"(g), "r"(sz));
}
__device__ __forceinline__ void cp_commit(){ asm volatile("cp.async.commit_group;\n"); }
template<int N> __device__ __forceinline__ void cp_wait(){ asm volatile("cp.async.wait_group %0;\n"::"n"(N)); }

// ---------------- kernels ----------------
__global__ void init_kernel(){
  if (threadIdx.x < 4) g_maxbits[threadIdx.x] = 0u;
}

__global__ void reduce_max_abs(const float* __restrict__ p, int n4, int which){
  const float4* p4 = (const float4*)p;
  float m = 0.f;
  for (int i = blockIdx.x*blockDim.x + threadIdx.x; i < n4; i += gridDim.x*blockDim.x){
    float4 v = p4[i];
    m = fmaxf(m, fmaxf(fmaxf(fabsf(v.x),fabsf(v.y)), fmaxf(fabsf(v.z),fabsf(v.w))));
  }
  #pragma unroll
  for (int o=16;o;o>>=1) m = fmaxf(m, __shfl_xor_sync(0xffffffffu, m, o));
  __shared__ float sm[8];
  if ((threadIdx.x & 31) == 0) sm[threadIdx.x>>5] = m;
  __syncthreads();
  if (threadIdx.x < 32){
    m = (threadIdx.x < (blockDim.x>>5)) ? sm[threadIdx.x] : 0.f;
    #pragma unroll
    for (int o=4;o;o>>=1) m = fmaxf(m, __shfl_xor_sync(0xffffffffu, m, o));
    if (threadIdx.x == 0) atomicMax(&g_maxbits[which], __float_as_uint(m));
  }
}

__global__ void prep_kernel(const float* __restrict__ g1, const float* __restrict__ b1,
                            const float* __restrict__ m1, const float* __restrict__ v1,
                            const float* __restrict__ g2, const float* __restrict__ b2,
                            const float* __restrict__ m2, const float* __restrict__ v2){
  int c = threadIdx.x;
  if (c < 3) g_scale[c] = (__uint_as_float(g_maxbits[c]) + 1e-12f) / 7.0f;
  if (c < Cc){
    float i1 = g1[c] / sqrtf(v1[c] + 1e-5f);
    g_inv1[c] = i1;  g_bias1[c] = b1[c] - m1[c]*i1;
    float i2 = g2[c] / sqrtf(v2[c] + 1e-5f);
    g_inv2[c] = i2;  g_bias2[c] = b2[c] - m2[c]*i2;
  }
}

// w OIHW -> int8 [co][(kh*3+kw)*256+ci]  (K-major for the GEMM B operand)
__global__ void quant_w_kernel(const float* __restrict__ w, int which){
  int i = blockIdx.x*blockDim.x + threadIdx.x;
  if (i >= Cc*KTOT) return;
  float alpha = __uint_as_float(g_maxbits[which]) + 1e-12f;
  float s = g_scale[which];
  int co = i / KTOT, k = i - co*KTOT;
  int pos = k >> 8, ci = k & 255;
  int kh = pos/3, kw = pos - kh*3;
  float v = w[((co*Cc + ci)*3 + kh)*3 + kw];
  v = fminf(fmaxf(v, -alpha), alpha);
  int8_t* dst = (which == 1) ? g_wq1 : g_wq2;
  dst[i] = (int8_t)__float2int_rn(v / s);
}

// x NCHW fp32 -> g_xq NHWC int8 (quantized), smem-transposed for coalescing
__global__ void quant_x_kernel(const float* __restrict__ x){
  __shared__ float tile[32][33];
  float alpha = __uint_as_float(g_maxbits[0]) + 1e-12f;
  float s = g_scale[0];
  int n = blockIdx.z;
  int hw0 = blockIdx.x*32, c0 = blockIdx.y*32;
  int tx = threadIdx.x, ty = threadIdx.y;
  #pragma unroll
  for (int j=0;j<4;j++){
    int c = c0 + ty + j*8, hw = hw0 + tx;
    tile[ty + j*8][tx] = (hw < HW) ? x[(n*Cc + c)*HW + hw] : 0.f;
  }
  __syncthreads();
  #pragma unroll
  for (int j=0;j<4;j++){
    int hw = hw0 + ty + j*8, c = c0 + tx;
    if (hw < HW){
      float v = tile[tx][ty + j*8];
      v = fminf(fmaxf(v, -alpha), alpha);
      g_xq[(n*HW + hw)*Cc + c] = (int8_t)__float2int_rn(v / s);
    }
  }
}

__global__ void quant_h_kernel(){
  int i = blockIdx.x*blockDim.x + threadIdx.x;
  if (i >= NELEM/4) return;
  float alpha = __uint_as_float(g_maxbits[3]) + 1e-12f;
  float s = alpha / 7.0f;
  float4 v = ((const float4*)g_h)[i];
  char4 q;
  q.x = (int8_t)__float2int_rn(fminf(fmaxf(v.x,-alpha),alpha) / s);
  q.y = (int8_t)__float2int_rn(fminf(fmaxf(v.y,-alpha),alpha) / s);
  q.z = (int8_t)__float2int_rn(fminf(fmaxf(v.z,-alpha),alpha) / s);
  q.w = (int8_t)__float2int_rn(fminf(fmaxf(v.w,-alpha),alpha) / s);
  ((char4*)g_hq)[i] = q;
}

// Implicit-GEMM 3x3 conv: M=pixels(NHW), N=out channels, K=2304.
// mode 1: A=g_xq, B=g_wq1, epilogue BN1+hardtanh -> g_h + max|h|
// mode 2: A=g_hq, B=g_wq2, epilogue scale only  -> g_y2
__global__ void __launch_bounds__(256,2) conv_kernel(int mode){
  const int8_t* __restrict__ Ain = (mode==1) ? g_xq : g_hq;
  const int8_t* __restrict__ Bw  = (mode==1) ? g_wq1 : g_wq2;
  __shared__ int8_t As[2][BM*AST];
  __shared__ int8_t Bs[2][BN*AST];
  __shared__ float s_inv[BN], s_bias[BN];

  int tid = threadIdx.x;
  int lane = tid & 31, wid = tid >> 5;
  int seg = tid & 3, r0 = tid >> 2, r1 = r0 + 64;
  int nb = blockIdx.y * BN;

  if (tid < BN){
    int c = nb + tid;
    s_inv[tid]  = g_inv1[c];
    s_bias[tid] = g_bias1[c];
  }

  // pixel decode for the two A rows this thread always loads
  int gm0 = blockIdx.x*BM + r0;
  int gm1 = gm0 + 64;
  int n0 = gm0/HW, rm0 = gm0 - n0*HW, y0 = rm0/Ww, x0c = rm0 - y0*Ww;
  int n1 = gm1/HW, rm1 = gm1 - n1*HW, y1 = rm1/Ww, x1c = rm1 - y1*Ww;

  auto loadTiles = [&](int ki, int st){
    int pos = ki >> 2;
    int p3 = pos/3;
    int kh = p3 - 1, kw = (pos - p3*3) - 1;
    int ciOff = ((ki & 3) << 6) + (seg << 4);
    {
      int sy = y0 + kh, sx = x0c + kw;
      bool v = ((unsigned)sy < Hh) & ((unsigned)sx < Ww);
      const int8_t* src = v ? (Ain + ((n0*HW + sy*Ww + sx)*Cc + ciOff)) : Ain;
      cp16(&As[st][r0*AST + (seg<<4)], src, v);
    }
    {
      int sy = y1 + kh, sx = x1c + kw;
      bool v = ((unsigned)sy < Hh) & ((unsigned)sx < Ww);
      const int8_t* src = v ? (Ain + ((n1*HW + sy*Ww + sx)*Cc + ciOff)) : Ain;
      cp16(&As[st][r1*AST + (seg<<4)], src, v);
    }
    cp16(&Bs[st][r0*AST + (seg<<4)], Bw + (nb + r0)*KTOT + ki*64 + (seg<<4), true);
    cp16(&Bs[st][r1*AST + (seg<<4)], Bw + (nb + r1)*KTOT + ki*64 + (seg<<4), true);
  };

  int acc[2][8][4];
  #pragma unroll
  for (int i=0;i<2;i++)
    #pragma unroll
    for (int j=0;j<8;j++)
      #pragma unroll
      for (int e=0;e<4;e++) acc[i][j][e] = 0;

  int wm = wid & 3, wn = wid >> 2;
  int mb = wm*32, nbw = wn*64;
  int gq = lane >> 2, tg = lane & 3;

  loadTiles(0, 0);
  cp_commit();

  for (int ki=0; ki<NKI; ki++){
    int st = ki & 1;
    if (ki+1 < NKI){ loadTiles(ki+1, st^1); cp_commit(); cp_wait<1>(); }
    else           { cp_wait<0>(); }
    __syncthreads();
    #pragma unroll
    for (int kk=0; kk<64; kk+=32){
      uint32_t a[2][4], b[8][2];
      #pragma unroll
      for (int im=0; im<2; im++){
        int row = mb + im*16 + gq;
        const int8_t* base = &As[st][0];
        a[im][0] = *(const uint32_t*)(base + row*AST + kk + tg*4);
        a[im][1] = *(const uint32_t*)(base + (row+8)*AST + kk + tg*4);
        a[im][2] = *(const uint32_t*)(base + row*AST + kk + 16 + tg*4);
        a[im][3] = *(const uint32_t*)(base + (row+8)*AST + kk + 16 + tg*4);
      }
      #pragma unroll
      for (int in_=0; in_<8; in_++){
        int col = nbw + in_*8 + gq;
        const int8_t* base = &Bs[st][0];
        b[in_][0] = *(const uint32_t*)(base + col*AST + kk + tg*4);
        b[in_][1] = *(const uint32_t*)(base + col*AST + kk + 16 + tg*4);
      }
      #pragma unroll
      for (int im=0; im<2; im++)
        #pragma unroll
        for (int in_=0; in_<8; in_++){
          asm volatile("mma.sync.aligned.m16n8k32.row.col.s32.s8.s8.s32 "
            "{%0,%1,%2,%3},{%4,%5,%6,%7},{%8,%9},{%0,%1,%2,%3};\n"
            : "+r"(acc[im][in_][0]),"+r"(acc[im][in_][1]),
              "+r"(acc[im][in_][2]),"+r"(acc[im][in_][3])
            : "r"(a[im][0]),"r"(a[im][1]),"r"(a[im][2]),"r"(a[im][3]),
              "r"(b[in_][0]),"r"(b[in_][1]));
        }
    }
    __syncthreads();
  }

  float sprod;
  if (mode==1) sprod = g_scale[0]*g_scale[1];
  else {
    float ah = __uint_as_float(g_maxbits[3]) + 1e-12f;
    sprod = (ah/7.0f) * g_scale[2];
  }
  float lmax = 0.f;
  #pragma unroll
  for (int im=0; im<2; im++)
    #pragma unroll
    for (int in_=0; in_<8; in_++)
      #pragma unroll
      for (int e=0; e<4; e++){
        int m  = mb  + im*16 + gq + (e>>1)*8;
        int nn = nbw + in_*8 + tg*2 + (e&1);
        int gm = blockIdx.x*BM + m;
        int co = nb + nn;
        float v = (float)acc[im][in_][e] * sprod;
        if (mode==1){
          v = v * s_inv[nn] + s_bias[nn];
          v = fminf(fmaxf(v, -1.f), 1.f);
          lmax = fmaxf(lmax, fabsf(v));
          g_h[gm*Cc + co] = v;
        } else {
          g_y2[gm*Cc + co] = v;
        }
      }
  if (mode==1){
    #pragma unroll
    for (int o=16;o;o>>=1) lmax = fmaxf(lmax, __shfl_xor_sync(0xffffffffu, lmax, o));
    if (lane==0) atomicMax(&g_maxbits[3], __float_as_uint(lmax));
  }
}

// out[n,c,h,w] = hardtanh( BN2( y2[n,hw,c] + x[n,c,hw] ) )   (NHWC->NCHW via smem)
__global__ void final_kernel(const float* __restrict__ x, float* __restrict__ out){
  __shared__ float tile[32][33];
  int n = blockIdx.z;
  int hw0 = blockIdx.x*32, c0 = blockIdx.y*32;
  int tx = threadIdx.x, ty = threadIdx.y;
  #pragma unroll
  for (int j=0;j<4;j++){
    int hw = hw0 + ty + j*8, c = c0 + tx;
    tile[ty + j*8][tx] = (hw < HW) ? g_y2[(n*HW + hw)*Cc + c] : 0.f;
  }
  __syncthreads();
  #pragma unroll
  for (int j=0;j<4;j++){
    int c = c0 + ty + j*8, hw = hw0 + tx;
    if (hw < HW){
      int idx = (n*Cc + c)*HW + hw;
      float v = tile[tx][ty + j*8] + x[idx];
      v = v * g_inv2[c] + g_bias2[c];
      out[idx] = fminf(fmaxf(v, -1.f), 1.f);
    }
  }
}

// ---------------- launch ----------------
extern "C" void kernel_launch(void* const* d_in, const int* in_sizes, int n_in,
                              void* d_out, int out_size){
  const float* x    = (const float*)d_in[0];
  const float* w1   = (const float*)d_in[1];
  const float* bn1g = (const float*)d_in[2];
  const float* bn1b = (const float*)d_in[3];
  const float* bn1m = (const float*)d_in[4];
  const float* bn1v = (const float*)d_in[5];
  const float* w2   = (const float*)d_in[6];
  const float* bn2g = (const float*)d_in[7];
  const float* bn2b = (const float*)d_in[8];
  const float* bn2m = (const float*)d_in[9];
  const float* bn2v = (const float*)d_in[10];
  float* out = (float*)d_out;

  init_kernel<<<1, 32>>>();
  reduce_max_abs<<<1024, 256>>>(x,  NELEM/4, 0);
  reduce_max_abs<<<256, 256>>>(w1, (Cc*KTOT)/4, 1);
  reduce_max_abs<<<256, 256>>>(w2, (Cc*KTOT)/4, 2);
  prep_kernel<<<1, 256>>>(bn1g, bn1b, bn1m, bn1v, bn2g, bn2b, bn2m, bn2v);
  quant_w_kernel<<<(Cc*KTOT + 255)/256, 256>>>(w1, 1);
  quant_w_kernel<<<(Cc*KTOT + 255)/256, 256>>>(w2, 2);
  quant_x_kernel<<<dim3(25, 8, 64), dim3(32, 8)>>>(x);
  conv_kernel<<<dim3(NPIX/BM, Cc/BN), 256>>>(1);
  quant_h_kernel<<<(NELEM/4 + 255)/256, 256>>>();
  conv_kernel<<<dim3(NPIX/BM, Cc/BN), 256>>>(2);
  final_kernel<<<dim3(25, 8, 64), dim3(32, 8)>>>(x, out);
}

// round 3
// speedup vs baseline: 1.0218x; 1.0218x over previous
#include <cuda_runtime.h>
#include <cstdint>

#define Bn   64
#define Cc   256
#define Hh   28
#define Ww   28
#define HW   784
#define NPIX 50176            // Bn*HW
#define KTOT 2304             // Cc*9
#define NELEM 12845056        // Bn*Cc*HW

#define BM 128
#define BN 128
#define BK 64
#define AST 80                // padded smem row stride (64B data + 16B pad)
#define NKI 36                // KTOT/BK
#define NST 4
#define TILEB (BM*AST)        // 10240
#define STAGEB (2*TILEB)      // 20480
#define SMEMB (NST*STAGEB)    // 81920

// ---------------- scratch (static device globals; allowed) ----------------
__device__ int8_t g_xq[(size_t)NPIX*Cc];
__device__ int8_t g_hq[(size_t)NPIX*Cc];
__device__ int8_t g_wq1[Cc*KTOT];
__device__ int8_t g_wq2[Cc*KTOT];
__device__ float  g_h [(size_t)NPIX*Cc];
__device__ float  g_y2[(size_t)NPIX*Cc];
__device__ float  g_inv1[Cc], g_bias1[Cc], g_inv2[Cc], g_bias2[Cc];
__device__ unsigned g_maxbits[4];   // 0:x 1:w1 2:w2 3:h
__device__ float  g_scale[3];

// ---------------- helpers ----------------
__device__ __forceinline__ unsigned smem_u32(const void* p){
  unsigned a;
  asm("{ .reg .u64 t; cvta.to.shared.u64 t, %1; cvt.u32.u64 %0, t; }" : "=r"(a) : "l"(p));
  return a;
}
__device__ __forceinline__ void cp16(void* sm, const void* g, bool v){
  unsigned sa = smem_u32(sm);
  int sz = v ? 16 : 0;
  asm volatile("cp.async.cg.shared.global [%0], [%1], 16, %2;\n" :: "r"(sa), "l"(g), "r"(sz));
}
__device__ __forceinline__ void cp_commitg(){ asm volatile("cp.async.commit_group;\n"); }
template<int N> __device__ __forceinline__ void cp_wait(){ asm volatile("cp.async.wait_group %0;\n"::"n"(N)); }
__device__ __forceinline__ void ldm4(uint32_t &r0, uint32_t &r1, uint32_t &r2, uint32_t &r3, unsigned a){
  asm volatile("ldmatrix.sync.aligned.m8n8.x4.shared.b16 {%0,%1,%2,%3}, [%4];"
    : "=r"(r0),"=r"(r1),"=r"(r2),"=r"(r3) : "r"(a));
}

// ---------------- small kernels ----------------
__global__ void init_kernel(){ if (threadIdx.x < 4) g_maxbits[threadIdx.x] = 0u; }

__device__ __forceinline__ void reduce_body(const float4* p4, int n4, int which){
  float m = 0.f;
  for (int i = blockIdx.x*blockDim.x + threadIdx.x; i < n4; i += gridDim.x*blockDim.x){
    float4 v = p4[i];
    m = fmaxf(m, fmaxf(fmaxf(fabsf(v.x),fabsf(v.y)), fmaxf(fabsf(v.z),fabsf(v.w))));
  }
  #pragma unroll
  for (int o=16;o;o>>=1) m = fmaxf(m, __shfl_xor_sync(0xffffffffu, m, o));
  __shared__ float sm[8];
  if ((threadIdx.x & 31) == 0) sm[threadIdx.x>>5] = m;
  __syncthreads();
  if (threadIdx.x < 32){
    m = (threadIdx.x < (blockDim.x>>5)) ? sm[threadIdx.x] : 0.f;
    #pragma unroll
    for (int o=4;o;o>>=1) m = fmaxf(m, __shfl_xor_sync(0xffffffffu, m, o));
    if (threadIdx.x == 0) atomicMax(&g_maxbits[which], __float_as_uint(m));
  }
}
__global__ void reduce_x_kernel(const float* __restrict__ x){
  reduce_body((const float4*)x, NELEM/4, 0);
}
__global__ void reduce_w_kernel(const float* __restrict__ w1, const float* __restrict__ w2){
  const float* w = blockIdx.y ? w2 : w1;
  reduce_body((const float4*)w, (Cc*KTOT)/4, 1 + blockIdx.y);
}

__global__ void prep_kernel(const float* __restrict__ g1, const float* __restrict__ b1,
                            const float* __restrict__ m1, const float* __restrict__ v1,
                            const float* __restrict__ g2, const float* __restrict__ b2,
                            const float* __restrict__ m2, const float* __restrict__ v2){
  int c = threadIdx.x;
  if (c < 3) g_scale[c] = (__uint_as_float(g_maxbits[c]) + 1e-12f) / 7.0f;
  if (c < Cc){
    float i1 = g1[c] / sqrtf(v1[c] + 1e-5f);
    g_inv1[c] = i1;  g_bias1[c] = b1[c] - m1[c]*i1;
    float i2 = g2[c] / sqrtf(v2[c] + 1e-5f);
    g_inv2[c] = i2;  g_bias2[c] = b2[c] - m2[c]*i2;
  }
}

// merged: w1-quant (blocks [0,2304)), w2-quant ([2304,4608)), x transpose-quant (rest)
#define WQB 2304
__global__ void quant_all_kernel(const float* __restrict__ w1, const float* __restrict__ w2,
                                 const float* __restrict__ x){
  __shared__ float tile[32][33];
  int b = blockIdx.x, tid = threadIdx.x;
  if (b < 2*WQB){
    int which = (b < WQB) ? 1 : 2;
    const float* w = (which == 1) ? w1 : w2;
    int i = (b - (which==2)*WQB)*256 + tid;
    float alpha = __uint_as_float(g_maxbits[which]) + 1e-12f;
    float s = g_scale[which];
    int co = i / KTOT, k = i - co*KTOT;
    int pos = k >> 8, ci = k & 255;
    int kh = pos/3, kw = pos - kh*3;
    float v = w[((co*Cc + ci)*3 + kh)*3 + kw];
    v = fminf(fmaxf(v, -alpha), alpha);
    int8_t* dst = (which == 1) ? g_wq1 : g_wq2;
    dst[i] = (int8_t)__float2int_rn(v / s);
  } else {
    int bb = b - 2*WQB;
    int n = bb/200; int r = bb - n*200; int by = r/25; int bx = r - by*25;
    float alpha = __uint_as_float(g_maxbits[0]) + 1e-12f;
    float s = g_scale[0];
    int hw0 = bx*32, c0 = by*32;
    int tx = tid & 31, ty = tid >> 5;
    #pragma unroll
    for (int j=0;j<4;j++){
      int c = c0 + ty + j*8, hw = hw0 + tx;
      tile[ty + j*8][tx] = (hw < HW) ? x[((size_t)n*Cc + c)*HW + hw] : 0.f;
    }
    __syncthreads();
    #pragma unroll
    for (int j=0;j<4;j++){
      int hw = hw0 + ty + j*8, c = c0 + tx;
      if (hw < HW){
        float v = tile[tx][ty + j*8];
        v = fminf(fmaxf(v, -alpha), alpha);
        g_xq[((size_t)n*HW + hw)*Cc + c] = (int8_t)__float2int_rn(v / s);
      }
    }
  }
}

__global__ void quant_h_kernel(){
  int i = blockIdx.x*blockDim.x + threadIdx.x;
  if (i >= NELEM/4) return;
  float alpha = __uint_as_float(g_maxbits[3]) + 1e-12f;
  float s = alpha / 7.0f;
  float4 v = ((const float4*)g_h)[i];
  char4 q;
  q.x = (int8_t)__float2int_rn(fminf(fmaxf(v.x,-alpha),alpha) / s);
  q.y = (int8_t)__float2int_rn(fminf(fmaxf(v.y,-alpha),alpha) / s);
  q.z = (int8_t)__float2int_rn(fminf(fmaxf(v.z,-alpha),alpha) / s);
  q.w = (int8_t)__float2int_rn(fminf(fmaxf(v.w,-alpha),alpha) / s);
  ((char4*)g_hq)[i] = q;
}

// ---------------- implicit-GEMM conv (IMMA, 4-stage cp.async, ldmatrix) ----------------
__global__ void __launch_bounds__(256,2) conv_kernel(int mode){
  extern __shared__ char dsm[];
  const int8_t* __restrict__ Ain = (mode==1) ? g_xq : g_hq;
  const int8_t* __restrict__ Bw  = (mode==1) ? g_wq1 : g_wq2;
  __shared__ float s_inv[BN], s_bias[BN];

  int tid = threadIdx.x;
  int lane = tid & 31, wid = tid >> 5;
  int seg = tid & 3, r0 = tid >> 2;       // loader: 4×16B segs per 64B row
  int nb = blockIdx.y * BN;

  if (mode==1 && tid < BN){
    int c = nb + tid;
    s_inv[tid]  = g_inv1[c];
    s_bias[tid] = g_bias1[c];
  }

  // pixel decode for the two A rows this thread loads (rows r0, r0+64)
  int gm0 = blockIdx.x*BM + r0;
  int gm1 = gm0 + 64;
  int n0 = gm0/HW, rm0 = gm0 - n0*HW, y0 = rm0/Ww, x0c = rm0 - y0*Ww;
  int n1 = gm1/HW, rm1 = gm1 - n1*HW, y1 = rm1/Ww, x1c = rm1 - y1*Ww;

  auto loadTiles = [&](int ki, int st){
    int pos = ki >> 2;
    int p3 = pos/3;
    int kh = p3 - 1, kw = (pos - p3*3) - 1;
    int ciOff = ((ki & 3) << 6) + (seg << 4);
    char* Abase = dsm + st*STAGEB;
    char* Bbase = Abase + TILEB;
    {
      int sy = y0 + kh, sx = x0c + kw;
      bool v = ((unsigned)sy < Hh) & ((unsigned)sx < Ww);
      const void* src = v ? (const void*)(Ain + ((size_t)(n0*HW + sy*Ww + sx)*Cc + ciOff))
                          : (const void*)Ain;
      cp16(Abase + r0*AST + (seg<<4), src, v);
    }
    {
      int sy = y1 + kh, sx = x1c + kw;
      bool v = ((unsigned)sy < Hh) & ((unsigned)sx < Ww);
      const void* src = v ? (const void*)(Ain + ((size_t)(n1*HW + sy*Ww + sx)*Cc + ciOff))
                          : (const void*)Ain;
      cp16(Abase + (r0+64)*AST + (seg<<4), src, v);
    }
    cp16(Bbase + r0*AST      + (seg<<4), Bw + (size_t)(nb + r0   )*KTOT + ki*64 + (seg<<4), true);
    cp16(Bbase + (r0+64)*AST + (seg<<4), Bw + (size_t)(nb + r0+64)*KTOT + ki*64 + (seg<<4), true);
  };

  int acc[2][8][4];
  #pragma unroll
  for (int i=0;i<2;i++)
    #pragma unroll
    for (int j=0;j<8;j++)
      #pragma unroll
      for (int e=0;e<4;e++) acc[i][j][e] = 0;

  int wm = wid & 3, wn = wid >> 2;
  int mb = wm*32, nbw = wn*64;
  int gq = lane >> 2, tg = lane & 3;

  // ldmatrix per-lane offsets (within a stage's A or B tile)
  int lr = (lane & 7) + ((lane >> 3) & 1)*8;   // row within 16-row tile
  int bo = (lane >> 4)*16;                      // byte-half offset
  unsigned sbase = smem_u32(dsm);
  unsigned aoff0 = (unsigned)((mb + lr)*AST + bo);          // im=0 (im=1: +16*AST)
  unsigned boff0 = (unsigned)((nbw + lr)*AST + bo) + TILEB; // pair=0 (pair p: +16*AST*p)

  loadTiles(0,0); cp_commitg();
  loadTiles(1,1); cp_commitg();
  loadTiles(2,2); cp_commitg();

  for (int ki=0; ki<NKI; ki++){
    if (ki < NKI-2)      cp_wait<2>();
    else if (ki == NKI-2) cp_wait<1>();
    else                  cp_wait<0>();
    __syncthreads();
    int nx = ki + 3;
    if (nx < NKI){ loadTiles(nx, nx & 3); cp_commitg(); }

    unsigned stb = sbase + (ki & 3)*STAGEB;
    #pragma unroll
    for (int kk=0; kk<64; kk+=32){
      uint32_t a[2][4], b[8][2];
      #pragma unroll
      for (int im=0; im<2; im++)
        ldm4(a[im][0], a[im][1], a[im][2], a[im][3],
             stb + aoff0 + (unsigned)(im*16*AST + kk));
      #pragma unroll
      for (int p=0; p<4; p++){
        uint32_t q0,q1,q2,q3;
        ldm4(q0,q1,q2,q3, stb + boff0 + (unsigned)(p*16*AST + kk));
        b[2*p][0]=q0; b[2*p+1][0]=q1; b[2*p][1]=q2; b[2*p+1][1]=q3;
      }
      #pragma unroll
      for (int im=0; im<2; im++)
        #pragma unroll
        for (int in_=0; in_<8; in_++){
          asm volatile("mma.sync.aligned.m16n8k32.row.col.s32.s8.s8.s32 "
            "{%0,%1,%2,%3},{%4,%5,%6,%7},{%8,%9},{%0,%1,%2,%3};\n"
            : "+r"(acc[im][in_][0]),"+r"(acc[im][in_][1]),
              "+r"(acc[im][in_][2]),"+r"(acc[im][in_][3])
            : "r"(a[im][0]),"r"(a[im][1]),"r"(a[im][2]),"r"(a[im][3]),
              "r"(b[in_][0]),"r"(b[in_][1]));
        }
    }
  }
  __syncthreads();

  float sprod;
  if (mode==1) sprod = g_scale[0]*g_scale[1];
  else {
    float ah = __uint_as_float(g_maxbits[3]) + 1e-12f;
    sprod = (ah/7.0f) * g_scale[2];
  }
  float lmax = 0.f;
  #pragma unroll
  for (int im=0; im<2; im++)
    #pragma unroll
    for (int in_=0; in_<8; in_++)
      #pragma unroll
      for (int half=0; half<2; half++){
        int m  = mb  + im*16 + gq + half*8;
        int nn = nbw + in_*8 + tg*2;
        int gm = blockIdx.x*BM + m;
        int co = nb + nn;
        float v0 = (float)acc[im][in_][half*2+0] * sprod;
        float v1 = (float)acc[im][in_][half*2+1] * sprod;
        if (mode==1){
          v0 = v0 * s_inv[nn]   + s_bias[nn];
          v1 = v1 * s_inv[nn+1] + s_bias[nn+1];
          v0 = fminf(fmaxf(v0, -1.f), 1.f);
          v1 = fminf(fmaxf(v1, -1.f), 1.f);
          lmax = fmaxf(lmax, fmaxf(fabsf(v0), fabsf(v1)));
          *(float2*)(g_h + (size_t)gm*Cc + co) = make_float2(v0, v1);
        } else {
          *(float2*)(g_y2 + (size_t)gm*Cc + co) = make_float2(v0, v1);
        }
      }
  if (mode==1){
    #pragma unroll
    for (int o=16;o;o>>=1) lmax = fmaxf(lmax, __shfl_xor_sync(0xffffffffu, lmax, o));
    if (lane==0) atomicMax(&g_maxbits[3], __float_as_uint(lmax));
  }
}

// out[n,c,h,w] = hardtanh( BN2( y2[n,hw,c] + x[n,c,hw] ) )
__global__ void final_kernel(const float* __restrict__ x, float* __restrict__ out){
  __shared__ float tile[32][33];
  int n = blockIdx.z;
  int hw0 = blockIdx.x*32, c0 = blockIdx.y*32;
  int tx = threadIdx.x, ty = threadIdx.y;
  #pragma unroll
  for (int j=0;j<4;j++){
    int hw = hw0 + ty + j*8, c = c0 + tx;
    tile[ty + j*8][tx] = (hw < HW) ? g_y2[((size_t)n*HW + hw)*Cc + c] : 0.f;
  }
  __syncthreads();
  #pragma unroll
  for (int j=0;j<4;j++){
    int c = c0 + ty + j*8, hw = hw0 + tx;
    if (hw < HW){
      size_t idx = ((size_t)n*Cc + c)*HW + hw;
      float v = tile[tx][ty + j*8] + x[idx];
      v = v * g_inv2[c] + g_bias2[c];
      out[idx] = fminf(fmaxf(v, -1.f), 1.f);
    }
  }
}

// ---------------- launch ----------------
extern "C" void kernel_launch(void* const* d_in, const int* in_sizes, int n_in,
                              void* d_out, int out_size){
  const float* x    = (const float*)d_in[0];
  const float* w1   = (const float*)d_in[1];
  const float* bn1g = (const float*)d_in[2];
  const float* bn1b = (const float*)d_in[3];
  const float* bn1m = (const float*)d_in[4];
  const float* bn1v = (const float*)d_in[5];
  const float* w2   = (const float*)d_in[6];
  const float* bn2g = (const float*)d_in[7];
  const float* bn2b = (const float*)d_in[8];
  const float* bn2m = (const float*)d_in[9];
  const float* bn2v = (const float*)d_in[10];
  float* out = (float*)d_out;

  static int cfg = 0;
  if (!cfg){
    cudaFuncSetAttribute(conv_kernel, cudaFuncAttributeMaxDynamicSharedMemorySize, SMEMB);
    cfg = 1;
  }

  init_kernel<<<1, 32>>>();                                    // 1
  reduce_x_kernel<<<1024, 256>>>(x);                           // 2
  reduce_w_kernel<<<dim3(256,2), 256>>>(w1, w2);               // 3
  prep_kernel<<<1, 256>>>(bn1g,bn1b,bn1m,bn1v,bn2g,bn2b,bn2m,bn2v); // 4
  quant_all_kernel<<<2*WQB + 12800, 256>>>(w1, w2, x);         // 5
  conv_kernel<<<dim3(NPIX/BM, Cc/BN), 256, SMEMB>>>(1);        // 6  <- ncu -s 5 -c 1 lands here
  quant_h_kernel<<<(NELEM/4 + 255)/256, 256>>>();              // 7
  conv_kernel<<<dim3(NPIX/BM, Cc/BN), 256, SMEMB>>>(2);        // 8
  final_kernel<<<dim3(25, 8, 64), dim3(32, 8)>>>(x, out);      // 9
}

// round 4
// speedup vs baseline: 1.0386x; 1.0164x over previous
#include <cuda_runtime.h>
#include <cstdint>

#define Bn   64
#define Cc   256
#define Hh   28
#define Ww   28
#define HW   784
#define NPIX 50176            // Bn*HW
#define KTOT 2304             // Cc*9
#define NELEM 12845056        // Bn*Cc*HW

#define BM 128
#define BN 128
#define BK 64
#define AST 80                // padded smem row stride (64B data + 16B pad)
#define NKI 36                // KTOT/BK
#define NST 4
#define TILEB (BM*AST)        // 10240
#define STAGEB (2*TILEB)      // 20480
#define SMEMB (NST*STAGEB)    // 81920

#define RXB 1024              // reduce blocks for x
#define RWB 18                // reduce blocks per w tensor

// ---------------- scratch (static device globals; allowed) ----------------
__device__ int8_t g_xq[(size_t)NPIX*Cc];
__device__ int8_t g_hq[(size_t)NPIX*Cc];
__device__ int8_t g_wq1[Cc*KTOT];
__device__ int8_t g_wq2[Cc*KTOT];
__device__ float  g_h [(size_t)NPIX*Cc];
__device__ float  g_y2[(size_t)NPIX*Cc];
__device__ float  g_inv1[Cc], g_bias1[Cc], g_inv2[Cc], g_bias2[Cc];
__device__ float  g_bmax[RXB + 2*RWB];   // per-block maxes (no atomics, no init)
__device__ unsigned g_maxbits[4];        // only [3] used (max|h|), zeroed in prep
__device__ float  g_scale[3];            // s_x, s_w1, s_w2 = alpha/7
__device__ float  g_alpha[3];            // alpha = max|.| + 1e-12

// ---------------- helpers ----------------
__device__ __forceinline__ unsigned smem_u32(const void* p){
  unsigned a;
  asm("{ .reg .u64 t; cvta.to.shared.u64 t, %1; cvt.u32.u64 %0, t; }" : "=r"(a) : "l"(p));
  return a;
}
__device__ __forceinline__ void cp16(void* sm, const void* g, bool v){
  unsigned sa = smem_u32(sm);
  int sz = v ? 16 : 0;
  asm volatile("cp.async.cg.shared.global [%0], [%1], 16, %2;\n" :: "r"(sa), "l"(g), "r"(sz));
}
__device__ __forceinline__ void cp_commitg(){ asm volatile("cp.async.commit_group;\n"); }
template<int N> __device__ __forceinline__ void cp_wait(){ asm volatile("cp.async.wait_group %0;\n"::"n"(N)); }
__device__ __forceinline__ void ldm4(uint32_t &r0, uint32_t &r1, uint32_t &r2, uint32_t &r3, unsigned a){
  asm volatile("ldmatrix.sync.aligned.m8n8.x4.shared.b16 {%0,%1,%2,%3}, [%4];"
    : "=r"(r0),"=r"(r1),"=r"(r2),"=r"(r3) : "r"(a));
}

// ---------------- launch #1: all three max-|.| reduces, per-block results ----------------
__global__ void reduce_all_kernel(const float* __restrict__ x,
                                  const float* __restrict__ w1,
                                  const float* __restrict__ w2){
  int b = blockIdx.x;
  const float4* p4;
  int n4, nb, lb;
  if (b < RXB){          p4 = (const float4*)x;  n4 = NELEM/4;       nb = RXB; lb = b; }
  else if (b < RXB+RWB){ p4 = (const float4*)w1; n4 = (Cc*KTOT)/4;   nb = RWB; lb = b - RXB; }
  else {                 p4 = (const float4*)w2; n4 = (Cc*KTOT)/4;   nb = RWB; lb = b - RXB - RWB; }
  float m = 0.f;
  for (int i = lb*blockDim.x + threadIdx.x; i < n4; i += nb*blockDim.x){
    float4 v = p4[i];
    m = fmaxf(m, fmaxf(fmaxf(fabsf(v.x),fabsf(v.y)), fmaxf(fabsf(v.z),fabsf(v.w))));
  }
  #pragma unroll
  for (int o=16;o;o>>=1) m = fmaxf(m, __shfl_xor_sync(0xffffffffu, m, o));
  __shared__ float sm[8];
  if ((threadIdx.x & 31) == 0) sm[threadIdx.x>>5] = m;
  __syncthreads();
  if (threadIdx.x == 0){
    #pragma unroll
    for (int i=1;i<8;i++) m = fmaxf(m, sm[i]);
    g_bmax[b] = m;
  }
}

// ---------------- launch #2: finish reduces + scales + BN constants ----------------
__global__ void prep_kernel(const float* __restrict__ g1, const float* __restrict__ b1,
                            const float* __restrict__ m1, const float* __restrict__ v1,
                            const float* __restrict__ g2, const float* __restrict__ b2,
                            const float* __restrict__ m2, const float* __restrict__ v2){
  __shared__ float red[8];
  int t = threadIdx.x, lane = t & 31, wid = t >> 5;
  float m = fmaxf(fmaxf(g_bmax[t], g_bmax[t+256]), fmaxf(g_bmax[t+512], g_bmax[t+768]));
  #pragma unroll
  for (int o=16;o;o>>=1) m = fmaxf(m, __shfl_xor_sync(0xffffffffu, m, o));
  if (lane == 0) red[wid] = m;
  __syncthreads();
  if (t == 0){
    #pragma unroll
    for (int i=1;i<8;i++) m = fmaxf(m, red[i]);
    float a = m + 1e-12f;
    g_alpha[0] = a;  g_scale[0] = a / 7.0f;
    g_maxbits[3] = 0u;
  }
  if (wid == 1){  // warp 1: both weight reductions
    float a1 = (lane < RWB) ? g_bmax[RXB + lane]       : 0.f;
    float a2 = (lane < RWB) ? g_bmax[RXB + RWB + lane] : 0.f;
    #pragma unroll
    for (int o=16;o;o>>=1){
      a1 = fmaxf(a1, __shfl_xor_sync(0xffffffffu, a1, o));
      a2 = fmaxf(a2, __shfl_xor_sync(0xffffffffu, a2, o));
    }
    if (lane == 0){
      float aa1 = a1 + 1e-12f, aa2 = a2 + 1e-12f;
      g_alpha[1] = aa1;  g_scale[1] = aa1 / 7.0f;
      g_alpha[2] = aa2;  g_scale[2] = aa2 / 7.0f;
    }
  }
  {
    int c = t;
    float i1 = g1[c] / sqrtf(v1[c] + 1e-5f);
    g_inv1[c] = i1;  g_bias1[c] = b1[c] - m1[c]*i1;
    float i2 = g2[c] / sqrtf(v2[c] + 1e-5f);
    g_inv2[c] = i2;  g_bias2[c] = b2[c] - m2[c]*i2;
  }
}

// ---------------- launch #3: quantize w1, w2, x (merged) ----------------
#define WQB 2304
__global__ void quant_all_kernel(const float* __restrict__ w1, const float* __restrict__ w2,
                                 const float* __restrict__ x){
  __shared__ float tile[32][33];
  int b = blockIdx.x, tid = threadIdx.x;
  if (b < 2*WQB){
    int which = (b < WQB) ? 1 : 2;
    const float* w = (which == 1) ? w1 : w2;
    int i = (b - (which==2)*WQB)*256 + tid;
    float alpha = g_alpha[which];
    float s = g_scale[which];
    int co = i / KTOT, k = i - co*KTOT;
    int pos = k >> 8, ci = k & 255;
    int kh = pos/3, kw = pos - kh*3;
    float v = w[((co*Cc + ci)*3 + kh)*3 + kw];
    v = fminf(fmaxf(v, -alpha), alpha);
    int8_t* dst = (which == 1) ? g_wq1 : g_wq2;
    dst[i] = (int8_t)__float2int_rn(v / s);
  } else {
    int bb = b - 2*WQB;
    int n = bb/200; int r = bb - n*200; int by = r/25; int bx = r - by*25;
    float alpha = g_alpha[0];
    float s = g_scale[0];
    int hw0 = bx*32, c0 = by*32;
    int tx = tid & 31, ty = tid >> 5;
    #pragma unroll
    for (int j=0;j<4;j++){
      int c = c0 + ty + j*8, hw = hw0 + tx;
      tile[ty + j*8][tx] = (hw < HW) ? x[((size_t)n*Cc + c)*HW + hw] : 0.f;
    }
    __syncthreads();
    #pragma unroll
    for (int j=0;j<4;j++){
      int hw = hw0 + ty + j*8, c = c0 + tx;
      if (hw < HW){
        float v = tile[tx][ty + j*8];
        v = fminf(fmaxf(v, -alpha), alpha);
        g_xq[((size_t)n*HW + hw)*Cc + c] = (int8_t)__float2int_rn(v / s);
      }
    }
  }
}

__global__ void quant_h_kernel(){
  int i = blockIdx.x*blockDim.x + threadIdx.x;
  if (i >= NELEM/4) return;
  float alpha = __uint_as_float(g_maxbits[3]) + 1e-12f;
  float s = alpha / 7.0f;
  float4 v = ((const float4*)g_h)[i];
  char4 q;
  q.x = (int8_t)__float2int_rn(fminf(fmaxf(v.x,-alpha),alpha) / s);
  q.y = (int8_t)__float2int_rn(fminf(fmaxf(v.y,-alpha),alpha) / s);
  q.z = (int8_t)__float2int_rn(fminf(fmaxf(v.z,-alpha),alpha) / s);
  q.w = (int8_t)__float2int_rn(fminf(fmaxf(v.w,-alpha),alpha) / s);
  ((char4*)g_hq)[i] = q;
}

// ---------------- implicit-GEMM conv (IMMA, 4-stage cp.async, ldmatrix) ----------------
__global__ void __launch_bounds__(256,2) conv_kernel(int mode){
  extern __shared__ char dsm[];
  const int8_t* __restrict__ Ain = (mode==1) ? g_xq : g_hq;
  const int8_t* __restrict__ Bw  = (mode==1) ? g_wq1 : g_wq2;
  __shared__ float s_inv[BN], s_bias[BN];

  int tid = threadIdx.x;
  int lane = tid & 31, wid = tid >> 5;
  int seg = tid & 3, r0 = tid >> 2;       // loader: 4×16B segs per 64B row
  int nb = blockIdx.y * BN;

  if (mode==1 && tid < BN){
    int c = nb + tid;
    s_inv[tid]  = g_inv1[c];
    s_bias[tid] = g_bias1[c];
  }

  int gm0 = blockIdx.x*BM + r0;
  int gm1 = gm0 + 64;
  int n0 = gm0/HW, rm0 = gm0 - n0*HW, y0 = rm0/Ww, x0c = rm0 - y0*Ww;
  int n1 = gm1/HW, rm1 = gm1 - n1*HW, y1 = rm1/Ww, x1c = rm1 - y1*Ww;

  auto loadTiles = [&](int ki, int st){
    int pos = ki >> 2;
    int p3 = pos/3;
    int kh = p3 - 1, kw = (pos - p3*3) - 1;
    int ciOff = ((ki & 3) << 6) + (seg << 4);
    char* Abase = dsm + st*STAGEB;
    char* Bbase = Abase + TILEB;
    {
      int sy = y0 + kh, sx = x0c + kw;
      bool v = ((unsigned)sy < Hh) & ((unsigned)sx < Ww);
      const void* src = v ? (const void*)(Ain + ((size_t)(n0*HW + sy*Ww + sx)*Cc + ciOff))
                          : (const void*)Ain;
      cp16(Abase + r0*AST + (seg<<4), src, v);
    }
    {
      int sy = y1 + kh, sx = x1c + kw;
      bool v = ((unsigned)sy < Hh) & ((unsigned)sx < Ww);
      const void* src = v ? (const void*)(Ain + ((size_t)(n1*HW + sy*Ww + sx)*Cc + ciOff))
                          : (const void*)Ain;
      cp16(Abase + (r0+64)*AST + (seg<<4), src, v);
    }
    cp16(Bbase + r0*AST      + (seg<<4), Bw + (size_t)(nb + r0   )*KTOT + ki*64 + (seg<<4), true);
    cp16(Bbase + (r0+64)*AST + (seg<<4), Bw + (size_t)(nb + r0+64)*KTOT + ki*64 + (seg<<4), true);
  };

  int acc[2][8][4];
  #pragma unroll
  for (int i=0;i<2;i++)
    #pragma unroll
    for (int j=0;j<8;j++)
      #pragma unroll
      for (int e=0;e<4;e++) acc[i][j][e] = 0;

  int wm = wid & 3, wn = wid >> 2;
  int mb = wm*32, nbw = wn*64;
  int gq = lane >> 2, tg = lane & 3;

  int lr = (lane & 7) + ((lane >> 3) & 1)*8;
  int bo = (lane >> 4)*16;
  unsigned sbase = smem_u32(dsm);
  unsigned aoff0 = (unsigned)((mb + lr)*AST + bo);
  unsigned boff0 = (unsigned)((nbw + lr)*AST + bo) + TILEB;

  loadTiles(0,0); cp_commitg();
  loadTiles(1,1); cp_commitg();
  loadTiles(2,2); cp_commitg();

  for (int ki=0; ki<NKI; ki++){
    if (ki < NKI-2)      cp_wait<2>();
    else if (ki == NKI-2) cp_wait<1>();
    else                  cp_wait<0>();
    __syncthreads();
    int nx = ki + 3;
    if (nx < NKI){ loadTiles(nx, nx & 3); cp_commitg(); }

    unsigned stb = sbase + (ki & 3)*STAGEB;
    #pragma unroll
    for (int kk=0; kk<64; kk+=32){
      uint32_t a[2][4], b[8][2];
      #pragma unroll
      for (int im=0; im<2; im++)
        ldm4(a[im][0], a[im][1], a[im][2], a[im][3],
             stb + aoff0 + (unsigned)(im*16*AST + kk));
      #pragma unroll
      for (int p=0; p<4; p++){
        uint32_t q0,q1,q2,q3;
        ldm4(q0,q1,q2,q3, stb + boff0 + (unsigned)(p*16*AST + kk));
        b[2*p][0]=q0; b[2*p+1][0]=q1; b[2*p][1]=q2; b[2*p+1][1]=q3;
      }
      #pragma unroll
      for (int im=0; im<2; im++)
        #pragma unroll
        for (int in_=0; in_<8; in_++){
          asm volatile("mma.sync.aligned.m16n8k32.row.col.s32.s8.s8.s32 "
            "{%0,%1,%2,%3},{%4,%5,%6,%7},{%8,%9},{%0,%1,%2,%3};\n"
            : "+r"(acc[im][in_][0]),"+r"(acc[im][in_][1]),
              "+r"(acc[im][in_][2]),"+r"(acc[im][in_][3])
            : "r"(a[im][0]),"r"(a[im][1]),"r"(a[im][2]),"r"(a[im][3]),
              "r"(b[in_][0]),"r"(b[in_][1]));
        }
    }
  }
  __syncthreads();

  float sprod;
  if (mode==1) sprod = g_scale[0]*g_scale[1];
  else {
    float ah = __uint_as_float(g_maxbits[3]) + 1e-12f;
    sprod = (ah/7.0f) * g_scale[2];
  }
  float lmax = 0.f;
  #pragma unroll
  for (int im=0; im<2; im++)
    #pragma unroll
    for (int in_=0; in_<8; in_++)
      #pragma unroll
      for (int half=0; half<2; half++){
        int m  = mb  + im*16 + gq + half*8;
        int nn = nbw + in_*8 + tg*2;
        int gm = blockIdx.x*BM + m;
        int co = nb + nn;
        float v0 = (float)acc[im][in_][half*2+0] * sprod;
        float v1 = (float)acc[im][in_][half*2+1] * sprod;
        if (mode==1){
          v0 = v0 * s_inv[nn]   + s_bias[nn];
          v1 = v1 * s_inv[nn+1] + s_bias[nn+1];
          v0 = fminf(fmaxf(v0, -1.f), 1.f);
          v1 = fminf(fmaxf(v1, -1.f), 1.f);
          lmax = fmaxf(lmax, fmaxf(fabsf(v0), fabsf(v1)));
          *(float2*)(g_h + (size_t)gm*Cc + co) = make_float2(v0, v1);
        } else {
          *(float2*)(g_y2 + (size_t)gm*Cc + co) = make_float2(v0, v1);
        }
      }
  if (mode==1){
    #pragma unroll
    for (int o=16;o;o>>=1) lmax = fmaxf(lmax, __shfl_xor_sync(0xffffffffu, lmax, o));
    if (lane==0) atomicMax(&g_maxbits[3], __float_as_uint(lmax));
  }
}

// out[n,c,h,w] = hardtanh( BN2( y2[n,hw,c] + x[n,c,hw] ) )
__global__ void final_kernel(const float* __restrict__ x, float* __restrict__ out){
  __shared__ float tile[32][33];
  int n = blockIdx.z;
  int hw0 = blockIdx.x*32, c0 = blockIdx.y*32;
  int tx = threadIdx.x, ty = threadIdx.y;
  #pragma unroll
  for (int j=0;j<4;j++){
    int hw = hw0 + ty + j*8, c = c0 + tx;
    tile[ty + j*8][tx] = (hw < HW) ? g_y2[((size_t)n*HW + hw)*Cc + c] : 0.f;
  }
  __syncthreads();
  #pragma unroll
  for (int j=0;j<4;j++){
    int c = c0 + ty + j*8, hw = hw0 + tx;
    if (hw < HW){
      size_t idx = ((size_t)n*Cc + c)*HW + hw;
      float v = tile[tx][ty + j*8] + x[idx];
      v = v * g_inv2[c] + g_bias2[c];
      out[idx] = fminf(fmaxf(v, -1.f), 1.f);
    }
  }
}

// ---------------- launch ----------------
extern "C" void kernel_launch(void* const* d_in, const int* in_sizes, int n_in,
                              void* d_out, int out_size){
  const float* x    = (const float*)d_in[0];
  const float* w1   = (const float*)d_in[1];
  const float* bn1g = (const float*)d_in[2];
  const float* bn1b = (const float*)d_in[3];
  const float* bn1m = (const float*)d_in[4];
  const float* bn1v = (const float*)d_in[5];
  const float* w2   = (const float*)d_in[6];
  const float* bn2g = (const float*)d_in[7];
  const float* bn2b = (const float*)d_in[8];
  const float* bn2m = (const float*)d_in[9];
  const float* bn2v = (const float*)d_in[10];
  float* out = (float*)d_out;

  static int cfg = 0;
  if (!cfg){
    cudaFuncSetAttribute(conv_kernel, cudaFuncAttributeMaxDynamicSharedMemorySize, SMEMB);
    cfg = 1;
  }

  reduce_all_kernel<<<RXB + 2*RWB, 256>>>(x, w1, w2);               // my #1
  prep_kernel<<<1, 256>>>(bn1g,bn1b,bn1m,bn1v,bn2g,bn2b,bn2m,bn2v); // my #2
  quant_all_kernel<<<2*WQB + 12800, 256>>>(w1, w2, x);              // my #3
  conv_kernel<<<dim3(NPIX/BM, Cc/BN), 256, SMEMB>>>(1);             // my #4 -> ncu slot 6
  quant_h_kernel<<<(NELEM/4 + 255)/256, 256>>>();                   // my #5
  conv_kernel<<<dim3(NPIX/BM, Cc/BN), 256, SMEMB>>>(2);             // my #6
  final_kernel<<<dim3(25, 8, 64), dim3(32, 8)>>>(x, out);           // my #7
}

// round 5
// speedup vs baseline: 1.1749x; 1.1312x over previous
#include <cuda_runtime.h>
#include <cstdint>

#define Bn   64
#define Cc   256
#define Hh   28
#define Ww   28
#define HW   784
#define NPIX 50176            // Bn*HW
#define KTOT 2304             // Cc*9
#define NELEM 12845056        // Bn*Cc*HW

#define BM 128
#define BN 64
#define AST 80                // padded smem row stride (64B data + 16B pad)
#define NKI 36                // KTOT/64
#define ATILE (BM*AST)        // 10240
#define STAGEB ((BM+BN)*AST)  // 15360
#define SMEMB (3*STAGEB)      // 46080  (3 stages; also >= 64*132*4 epilogue tile)

#define RXB 1024
#define RWB 18

// ---------------- scratch (static device globals; allowed) ----------------
__device__ int8_t g_xq[(size_t)NPIX*Cc];
__device__ int8_t g_hq[(size_t)NPIX*Cc];
__device__ int8_t g_wq1[Cc*KTOT];
__device__ int8_t g_wq2[Cc*KTOT];
__device__ float  g_h [(size_t)NPIX*Cc];
__device__ float  g_inv1[Cc], g_bias1[Cc], g_inv2[Cc], g_bias2[Cc];
__device__ float  g_bmax[RXB + 2*RWB];
__device__ unsigned g_maxbits[4];        // only [3]: max|h|, zeroed in prep
__device__ float  g_scale[3];
__device__ float  g_alpha[3];

// ---------------- helpers ----------------
__device__ __forceinline__ unsigned smem_u32(const void* p){
  unsigned a;
  asm("{ .reg .u64 t; cvta.to.shared.u64 t, %1; cvt.u32.u64 %0, t; }" : "=r"(a) : "l"(p));
  return a;
}
__device__ __forceinline__ void cp16(void* sm, const void* g, bool v){
  unsigned sa = smem_u32(sm);
  int sz = v ? 16 : 0;
  asm volatile("cp.async.cg.shared.global [%0], [%1], 16, %2;\n" :: "r"(sa), "l"(g), "r"(sz));
}
__device__ __forceinline__ void cp_commitg(){ asm volatile("cp.async.commit_group;\n"); }
template<int N> __device__ __forceinline__ void cp_wait(){ asm volatile("cp.async.wait_group %0;\n"::"n"(N)); }
__device__ __forceinline__ void ldm4(uint32_t &r0, uint32_t &r1, uint32_t &r2, uint32_t &r3, unsigned a){
  asm volatile("ldmatrix.sync.aligned.m8n8.x4.shared.b16 {%0,%1,%2,%3}, [%4];"
    : "=r"(r0),"=r"(r1),"=r"(r2),"=r"(r3) : "r"(a));
}

// ---------------- launch #1: merged max-|.| reduces ----------------
__global__ void reduce_all_kernel(const float* __restrict__ x,
                                  const float* __restrict__ w1,
                                  const float* __restrict__ w2){
  int b = blockIdx.x;
  const float4* p4;
  int n4, nb, lb;
  if (b < RXB){          p4 = (const float4*)x;  n4 = NELEM/4;     nb = RXB; lb = b; }
  else if (b < RXB+RWB){ p4 = (const float4*)w1; n4 = (Cc*KTOT)/4; nb = RWB; lb = b - RXB; }
  else {                 p4 = (const float4*)w2; n4 = (Cc*KTOT)/4; nb = RWB; lb = b - RXB - RWB; }
  float m = 0.f;
  for (int i = lb*blockDim.x + threadIdx.x; i < n4; i += nb*blockDim.x){
    float4 v = p4[i];
    m = fmaxf(m, fmaxf(fmaxf(fabsf(v.x),fabsf(v.y)), fmaxf(fabsf(v.z),fabsf(v.w))));
  }
  #pragma unroll
  for (int o=16;o;o>>=1) m = fmaxf(m, __shfl_xor_sync(0xffffffffu, m, o));
  __shared__ float sm[8];
  if ((threadIdx.x & 31) == 0) sm[threadIdx.x>>5] = m;
  __syncthreads();
  if (threadIdx.x == 0){
    #pragma unroll
    for (int i=1;i<8;i++) m = fmaxf(m, sm[i]);
    g_bmax[b] = m;
  }
}

// ---------------- launch #2: finish reduces + scales + BN constants ----------------
__global__ void prep_kernel(const float* __restrict__ g1, const float* __restrict__ b1,
                            const float* __restrict__ m1, const float* __restrict__ v1,
                            const float* __restrict__ g2, const float* __restrict__ b2,
                            const float* __restrict__ m2, const float* __restrict__ v2){
  __shared__ float red[8];
  int t = threadIdx.x, lane = t & 31, wid = t >> 5;
  float m = fmaxf(fmaxf(g_bmax[t], g_bmax[t+256]), fmaxf(g_bmax[t+512], g_bmax[t+768]));
  #pragma unroll
  for (int o=16;o;o>>=1) m = fmaxf(m, __shfl_xor_sync(0xffffffffu, m, o));
  if (lane == 0) red[wid] = m;
  __syncthreads();
  if (t == 0){
    #pragma unroll
    for (int i=1;i<8;i++) m = fmaxf(m, red[i]);
    float a = m + 1e-12f;
    g_alpha[0] = a;  g_scale[0] = a / 7.0f;
    g_maxbits[3] = 0u;
  }
  if (wid == 1){
    float a1 = (lane < RWB) ? g_bmax[RXB + lane]       : 0.f;
    float a2 = (lane < RWB) ? g_bmax[RXB + RWB + lane] : 0.f;
    #pragma unroll
    for (int o=16;o;o>>=1){
      a1 = fmaxf(a1, __shfl_xor_sync(0xffffffffu, a1, o));
      a2 = fmaxf(a2, __shfl_xor_sync(0xffffffffu, a2, o));
    }
    if (lane == 0){
      float aa1 = a1 + 1e-12f, aa2 = a2 + 1e-12f;
      g_alpha[1] = aa1;  g_scale[1] = aa1 / 7.0f;
      g_alpha[2] = aa2;  g_scale[2] = aa2 / 7.0f;
    }
  }
  {
    int c = t;
    float i1 = g1[c] / sqrtf(v1[c] + 1e-5f);
    g_inv1[c] = i1;  g_bias1[c] = b1[c] - m1[c]*i1;
    float i2 = g2[c] / sqrtf(v2[c] + 1e-5f);
    g_inv2[c] = i2;  g_bias2[c] = b2[c] - m2[c]*i2;
  }
}

// ---------------- launch #3: quantize w1, w2, x ----------------
#define WQB 2304
__global__ void quant_all_kernel(const float* __restrict__ w1, const float* __restrict__ w2,
                                 const float* __restrict__ x){
  __shared__ float tile[32][33];
  int b = blockIdx.x, tid = threadIdx.x;
  if (b < 2*WQB){
    int which = (b < WQB) ? 1 : 2;
    const float* w = (which == 1) ? w1 : w2;
    int i = (b - (which==2)*WQB)*256 + tid;
    float alpha = g_alpha[which];
    float s = g_scale[which];
    int co = i / KTOT, k = i - co*KTOT;
    int pos = k >> 8, ci = k & 255;
    int kh = pos/3, kw = pos - kh*3;
    float v = w[((co*Cc + ci)*3 + kh)*3 + kw];
    v = fminf(fmaxf(v, -alpha), alpha);
    int8_t* dst = (which == 1) ? g_wq1 : g_wq2;
    dst[i] = (int8_t)__float2int_rn(v / s);
  } else {
    int bb = b - 2*WQB;
    int n = bb/200; int r = bb - n*200; int by = r/25; int bx = r - by*25;
    float alpha = g_alpha[0];
    float s = g_scale[0];
    int hw0 = bx*32, c0 = by*32;
    int tx = tid & 31, ty = tid >> 5;
    #pragma unroll
    for (int j=0;j<4;j++){
      int c = c0 + ty + j*8, hw = hw0 + tx;
      tile[ty + j*8][tx] = (hw < HW) ? x[((size_t)n*Cc + c)*HW + hw] : 0.f;
    }
    __syncthreads();
    #pragma unroll
    for (int j=0;j<4;j++){
      int hw = hw0 + ty + j*8, c = c0 + tx;
      if (hw < HW){
        float v = tile[tx][ty + j*8];
        v = fminf(fmaxf(v, -alpha), alpha);
        g_xq[((size_t)n*HW + hw)*Cc + c] = (int8_t)__float2int_rn(v / s);
      }
    }
  }
}

__global__ void quant_h_kernel(){
  int i = blockIdx.x*blockDim.x + threadIdx.x;
  if (i >= NELEM/4) return;
  float alpha = __uint_as_float(g_maxbits[3]) + 1e-12f;
  float s = alpha / 7.0f;
  float4 v = ((const float4*)g_h)[i];
  char4 q;
  q.x = (int8_t)__float2int_rn(fminf(fmaxf(v.x,-alpha),alpha) / s);
  q.y = (int8_t)__float2int_rn(fminf(fmaxf(v.y,-alpha),alpha) / s);
  q.z = (int8_t)__float2int_rn(fminf(fmaxf(v.z,-alpha),alpha) / s);
  q.w = (int8_t)__float2int_rn(fminf(fmaxf(v.w,-alpha),alpha) / s);
  ((char4*)g_hq)[i] = q;
}

// ---------------- implicit-GEMM conv: CTA 128x64, 8 warps of 32x32, 3-stage ----------------
// MODE 1: A=g_xq, B=g_wq1; epilogue BN1+hardtanh -> g_h (NHWC) + max|h|
// MODE 2: A=g_hq, B=g_wq2; epilogue +residual, BN2, hardtanh -> out (NCHW via smem transpose)
template<int MODE>
__global__ void __launch_bounds__(256,3) conv_kernel(const float* __restrict__ xres,
                                                     float* __restrict__ out){
  extern __shared__ char dsm[];
  const int8_t* __restrict__ Ain = (MODE==1) ? g_xq : g_hq;
  const int8_t* __restrict__ Bw  = (MODE==1) ? g_wq1 : g_wq2;
  __shared__ float s_inv[BN], s_bias[BN];

  int tid = threadIdx.x;
  int lane = tid & 31, wid = tid >> 5;
  int seg = tid & 3, r0 = tid >> 2;       // 4x16B segs per 64B row; r0: 0..63
  int nb = blockIdx.y * BN;

  if (MODE==1 && tid < BN){
    int c = nb + tid;
    s_inv[tid]  = g_inv1[c];
    s_bias[tid] = g_bias1[c];
  }

  int gm0 = blockIdx.x*BM + r0;
  int gm1 = gm0 + 64;
  int n0 = gm0/HW, rm0 = gm0 - n0*HW, y0 = rm0/Ww, x0c = rm0 - y0*Ww;
  int n1 = gm1/HW, rm1 = gm1 - n1*HW, y1 = rm1/Ww, x1c = rm1 - y1*Ww;

  auto loadTiles = [&](int ki, int st){
    int pos = ki >> 2;
    int p3 = pos/3;
    int kh = p3 - 1, kw = (pos - p3*3) - 1;
    int ciOff = ((ki & 3) << 6) + (seg << 4);
    char* Abase = dsm + st*STAGEB;
    char* Bbase = Abase + ATILE;
    {
      int sy = y0 + kh, sx = x0c + kw;
      bool v = ((unsigned)sy < Hh) & ((unsigned)sx < Ww);
      const void* src = v ? (const void*)(Ain + ((size_t)(n0*HW + sy*Ww + sx)*Cc + ciOff))
                          : (const void*)Ain;
      cp16(Abase + r0*AST + (seg<<4), src, v);
    }
    {
      int sy = y1 + kh, sx = x1c + kw;
      bool v = ((unsigned)sy < Hh) & ((unsigned)sx < Ww);
      const void* src = v ? (const void*)(Ain + ((size_t)(n1*HW + sy*Ww + sx)*Cc + ciOff))
                          : (const void*)Ain;
      cp16(Abase + (r0+64)*AST + (seg<<4), src, v);
    }
    cp16(Bbase + r0*AST + (seg<<4), Bw + (size_t)(nb + r0)*KTOT + ki*64 + (seg<<4), true);
  };

  int acc[2][4][4];
  #pragma unroll
  for (int i=0;i<2;i++)
    #pragma unroll
    for (int j=0;j<4;j++)
      #pragma unroll
      for (int e=0;e<4;e++) acc[i][j][e] = 0;

  int wm = wid & 3, wn = wid >> 2;
  int mb = wm*32, nbw = wn*32;
  int gq = lane >> 2, tg = lane & 3;

  int lr = (lane & 7) + ((lane >> 3) & 1)*8;
  int bo = (lane >> 4)*16;
  unsigned sbase = smem_u32(dsm);
  unsigned aoff0 = (unsigned)((mb + lr)*AST + bo);
  unsigned boff0 = (unsigned)((nbw + lr)*AST + bo) + ATILE;

  loadTiles(0,0); cp_commitg();
  loadTiles(1,1); cp_commitg();

  int st = 0;
  for (int ki=0; ki<NKI; ki++){
    if (ki < NKI-1) cp_wait<1>(); else cp_wait<0>();
    __syncthreads();
    int nx = ki + 2;
    int nst = st + 2; if (nst >= 3) nst -= 3;
    if (nx < NKI){ loadTiles(nx, nst); cp_commitg(); }

    unsigned stb = sbase + st*STAGEB;
    #pragma unroll
    for (int kk=0; kk<64; kk+=32){
      uint32_t a[2][4], b[4][2];
      #pragma unroll
      for (int im=0; im<2; im++)
        ldm4(a[im][0], a[im][1], a[im][2], a[im][3],
             stb + aoff0 + (unsigned)(im*16*AST + kk));
      #pragma unroll
      for (int p=0; p<2; p++){
        uint32_t q0,q1,q2,q3;
        ldm4(q0,q1,q2,q3, stb + boff0 + (unsigned)(p*16*AST + kk));
        b[2*p][0]=q0; b[2*p+1][0]=q1; b[2*p][1]=q2; b[2*p+1][1]=q3;
      }
      #pragma unroll
      for (int im=0; im<2; im++)
        #pragma unroll
        for (int in_=0; in_<4; in_++){
          asm volatile("mma.sync.aligned.m16n8k32.row.col.s32.s8.s8.s32 "
            "{%0,%1,%2,%3},{%4,%5,%6,%7},{%8,%9},{%0,%1,%2,%3};\n"
            : "+r"(acc[im][in_][0]),"+r"(acc[im][in_][1]),
              "+r"(acc[im][in_][2]),"+r"(acc[im][in_][3])
            : "r"(a[im][0]),"r"(a[im][1]),"r"(a[im][2]),"r"(a[im][3]),
              "r"(b[in_][0]),"r"(b[in_][1]));
        }
    }
    st++; if (st >= 3) st = 0;
  }
  __syncthreads();   // all compute done; stage smem free for reuse

  if (MODE == 1){
    float sprod = g_scale[0]*g_scale[1];
    float lmax = 0.f;
    #pragma unroll
    for (int im=0; im<2; im++)
      #pragma unroll
      for (int in_=0; in_<4; in_++)
        #pragma unroll
        for (int half=0; half<2; half++){
          int m  = mb  + im*16 + gq + half*8;
          int nn = nbw + in_*8 + tg*2;
          int gm = blockIdx.x*BM + m;
          int co = nb + nn;
          float v0 = (float)acc[im][in_][half*2+0] * sprod;
          float v1 = (float)acc[im][in_][half*2+1] * sprod;
          v0 = v0 * s_inv[nn]   + s_bias[nn];
          v1 = v1 * s_inv[nn+1] + s_bias[nn+1];
          v0 = fminf(fmaxf(v0, -1.f), 1.f);
          v1 = fminf(fmaxf(v1, -1.f), 1.f);
          lmax = fmaxf(lmax, fmaxf(fabsf(v0), fabsf(v1)));
          *(float2*)(g_h + (size_t)gm*Cc + co) = make_float2(v0, v1);
        }
    #pragma unroll
    for (int o=16;o;o>>=1) lmax = fmaxf(lmax, __shfl_xor_sync(0xffffffffu, lmax, o));
    if (lane==0) atomicMax(&g_maxbits[3], __float_as_uint(lmax));
  } else {
    // fused: y2 -> smem [c][pix] -> +residual, BN2, hardtanh -> NCHW out
    float ah = __uint_as_float(g_maxbits[3]) + 1e-12f;
    float sprod = (ah/7.0f) * g_scale[2];
    float* tp = (float*)dsm;               // [64][132]
    #pragma unroll
    for (int im=0; im<2; im++)
      #pragma unroll
      for (int in_=0; in_<4; in_++)
        #pragma unroll
        for (int half=0; half<2; half++){
          int m  = mb  + im*16 + gq + half*8;
          int nn = nbw + in_*8 + tg*2;
          tp[(nn  )*132 + m] = (float)acc[im][in_][half*2+0] * sprod;
          tp[(nn+1)*132 + m] = (float)acc[im][in_][half*2+1] * sprod;
        }
    __syncthreads();
    #pragma unroll
    for (int j=0;j<8;j++){
      int task = j*256 + tid;
      int c = task >> 5;                   // 0..63
      int pix = (task & 31)*4;             // 0..124
      int gmb = blockIdx.x*BM + pix;
      int n = gmb/HW, hw = gmb - n*HW;     // float4 never crosses n (hw mult of 4, HW mult of 4)
      int cg = nb + c;
      float inv = g_inv2[cg], bia = g_bias2[cg];
      float4 y = *(const float4*)(tp + c*132 + pix);
      size_t idx = ((size_t)n*Cc + cg)*HW + hw;
      float4 r = *(const float4*)(xres + idx);
      float4 o;
      o.x = fminf(fmaxf((y.x + r.x)*inv + bia, -1.f), 1.f);
      o.y = fminf(fmaxf((y.y + r.y)*inv + bia, -1.f), 1.f);
      o.z = fminf(fmaxf((y.z + r.z)*inv + bia, -1.f), 1.f);
      o.w = fminf(fmaxf((y.w + r.w)*inv + bia, -1.f), 1.f);
      *(float4*)(out + idx) = o;
    }
  }
}

// ---------------- launch ----------------
extern "C" void kernel_launch(void* const* d_in, const int* in_sizes, int n_in,
                              void* d_out, int out_size){
  const float* x    = (const float*)d_in[0];
  const float* w1   = (const float*)d_in[1];
  const float* bn1g = (const float*)d_in[2];
  const float* bn1b = (const float*)d_in[3];
  const float* bn1m = (const float*)d_in[4];
  const float* bn1v = (const float*)d_in[5];
  const float* w2   = (const float*)d_in[6];
  const float* bn2g = (const float*)d_in[7];
  const float* bn2b = (const float*)d_in[8];
  const float* bn2m = (const float*)d_in[9];
  const float* bn2v = (const float*)d_in[10];
  float* out = (float*)d_out;

  static int cfg = 0;
  if (!cfg){
    cudaFuncSetAttribute(conv_kernel<1>, cudaFuncAttributeMaxDynamicSharedMemorySize, SMEMB);
    cudaFuncSetAttribute(conv_kernel<2>, cudaFuncAttributeMaxDynamicSharedMemorySize, SMEMB);
    cfg = 1;
  }

  reduce_all_kernel<<<RXB + 2*RWB, 256>>>(x, w1, w2);               // my #1
  prep_kernel<<<1, 256>>>(bn1g,bn1b,bn1m,bn1v,bn2g,bn2b,bn2m,bn2v); // my #2
  quant_all_kernel<<<2*WQB + 12800, 256>>>(w1, w2, x);              // my #3
  conv_kernel<1><<<dim3(NPIX/BM, Cc/BN), 256, SMEMB>>>(x, out);     // my #4 -> ncu slot 6
  quant_h_kernel<<<(NELEM/4 + 255)/256, 256>>>();                   // my #5
  conv_kernel<2><<<dim3(NPIX/BM, Cc/BN), 256, SMEMB>>>(x, out);     // my #6
}